// round 3
// baseline (speedup 1.0000x reference)
#include <cuda_runtime.h>
#include <cuda_bf16.h>
#include <math.h>

// SimDiff: right[f,i] = cos(x[f,i], x[f+interval, i+1])        (i < tpf-1)
//          down [f,i] = cos(x[f,i], x[f+interval, i+width])    (i < tpf-width)
// all other positions -1. Output: [right_full | down_full], each frames*tpf f32.
//
// One warp per token, streaming all three vectors with PREFETCH-DEPTH-2
// double buffering: 6 float4 loads (a/b/c x 2 iterations) in flight per warp
// at all times -> MLP 6/warp. __launch_bounds__(256,5) keeps regs <= 51 so
// 5 CTAs/SM (40 warps) stay resident: ~30KB of loads in flight per SM,
// enough to saturate the DRAM/LTS path instead of being latency-bound.

#define EPSN 1e-8f

template <int NPL>  // float4 elements per lane; D = NPL * 128
__global__ void __launch_bounds__(256, 5) simdiff_pf2_kernel(
    const float* __restrict__ x,
    const int* __restrict__ p_frames,
    const int* __restrict__ p_height,
    const int* __restrict__ p_width,
    const int* __restrict__ p_interval,
    float* __restrict__ out,
    int total)  // frames * tpf
{
    const int gwarp = (blockIdx.x * blockDim.x + threadIdx.x) >> 5;
    const int lane  = threadIdx.x & 31;
    if (gwarp >= total) return;

    const int width    = *p_width;
    const int height   = *p_height;
    const int frames   = *p_frames;
    const int interval = *p_interval;
    const int tpf      = width * height;
    const int D        = NPL * 128;

    const int f = gwarp / tpf;
    const int i = gwarp - f * tpf;

    float* __restrict__ outR = out;
    float* __restrict__ outD = out + total;

    const bool vf = (f + interval) < frames;
    if (!vf) {
        if (lane == 0) { outR[gwarp] = -1.0f; outD[gwarp] = -1.0f; }
        return;
    }
    const bool vr = (i < tpf - 1);
    const bool vd = (i < tpf - width);

    const size_t bframe = (size_t)(f + interval) * tpf + i;
    // Clamp invalid neighbors to a safe in-bounds vector; fixed up at the end.
    const size_t i1 = vr ? (bframe + 1)     : bframe;
    const size_t i2 = vd ? (bframe + width) : bframe;

    const float4* __restrict__ a4 =
        reinterpret_cast<const float4*>(x + (size_t)gwarp * D) + lane;
    const float4* __restrict__ b4 =
        reinterpret_cast<const float4*>(x + i1 * D) + lane;
    const float4* __restrict__ c4 =
        reinterpret_cast<const float4*>(x + i2 * D) + lane;

    float na = 0.0f, d1 = 0.0f, n1 = 0.0f, d2 = 0.0f, n2 = 0.0f;

    // Prefetch depth 2: two iterations' worth of loads always outstanding.
    float4 a0 = a4[0],  b0 = b4[0],  c0 = c4[0];
    float4 a1, b1, c1;
    if (NPL > 1) { a1 = a4[32]; b1 = b4[32]; c1 = c4[32]; }

#pragma unroll
    for (int k = 0; k < NPL; k++) {
        // Consume buffer for iteration k.
        float4 ac = a0, bc = b0, cc = c0;
        // Rotate: slot1 -> slot0, issue loads for k+2 into slot1.
        a0 = a1; b0 = b1; c0 = c1;
        if (k + 2 < NPL) {
            a1 = a4[32 * (k + 2)];
            b1 = b4[32 * (k + 2)];
            c1 = c4[32 * (k + 2)];
        }

        na = fmaf(ac.x, ac.x, na); na = fmaf(ac.y, ac.y, na);
        na = fmaf(ac.z, ac.z, na); na = fmaf(ac.w, ac.w, na);
        d1 = fmaf(ac.x, bc.x, d1); d1 = fmaf(ac.y, bc.y, d1);
        d1 = fmaf(ac.z, bc.z, d1); d1 = fmaf(ac.w, bc.w, d1);
        n1 = fmaf(bc.x, bc.x, n1); n1 = fmaf(bc.y, bc.y, n1);
        n1 = fmaf(bc.z, bc.z, n1); n1 = fmaf(bc.w, bc.w, n1);
        d2 = fmaf(ac.x, cc.x, d2); d2 = fmaf(ac.y, cc.y, d2);
        d2 = fmaf(ac.z, cc.z, d2); d2 = fmaf(ac.w, cc.w, d2);
        n2 = fmaf(cc.x, cc.x, n2); n2 = fmaf(cc.y, cc.y, n2);
        n2 = fmaf(cc.z, cc.z, n2); n2 = fmaf(cc.w, cc.w, n2);
    }

    // Warp butterfly reduce 5 accumulators.
#pragma unroll
    for (int off = 16; off > 0; off >>= 1) {
        na += __shfl_xor_sync(0xFFFFFFFFu, na, off);
        d1 += __shfl_xor_sync(0xFFFFFFFFu, d1, off);
        n1 += __shfl_xor_sync(0xFFFFFFFFu, n1, off);
        d2 += __shfl_xor_sync(0xFFFFFFFFu, d2, off);
        n2 += __shfl_xor_sync(0xFFFFFFFFu, n2, off);
    }

    if (lane == 0) {
        const float nA = fmaxf(sqrtf(na), EPSN);
        outR[gwarp] = vr ? d1 / (nA * fmaxf(sqrtf(n1), EPSN)) : -1.0f;
        outD[gwarp] = vd ? d2 / (nA * fmaxf(sqrtf(n2), EPSN)) : -1.0f;
    }
}

// Generic fallback for arbitrary D (scalar loads).
__global__ void __launch_bounds__(256) simdiff_generic_kernel(
    const float* __restrict__ x,
    const int* __restrict__ p_frames,
    const int* __restrict__ p_height,
    const int* __restrict__ p_width,
    const int* __restrict__ p_interval,
    float* __restrict__ out,
    int total, int D)
{
    const int gwarp = (blockIdx.x * blockDim.x + threadIdx.x) >> 5;
    const int lane  = threadIdx.x & 31;
    if (gwarp >= total) return;

    const int width    = *p_width;
    const int height   = *p_height;
    const int frames   = *p_frames;
    const int interval = *p_interval;
    const int tpf      = width * height;

    const int f = gwarp / tpf;
    const int i = gwarp - f * tpf;

    float* __restrict__ outR = out;
    float* __restrict__ outD = out + total;

    const bool vf = (f + interval) < frames;
    if (!vf) {
        if (lane == 0) { outR[gwarp] = -1.0f; outD[gwarp] = -1.0f; }
        return;
    }
    const bool vr = (i < tpf - 1);
    const bool vd = (i < tpf - width);

    const size_t bframe = (size_t)(f + interval) * tpf + i;
    const size_t i1 = vr ? (bframe + 1)     : bframe;
    const size_t i2 = vd ? (bframe + width) : bframe;

    const float* a = x + (size_t)gwarp * D;
    const float* b = x + i1 * D;
    const float* c = x + i2 * D;

    float na = 0.0f, d1 = 0.0f, n1 = 0.0f, d2 = 0.0f, n2 = 0.0f;
    for (int k = lane; k < D; k += 32) {
        float av = a[k], bv = b[k], cv = c[k];
        na = fmaf(av, av, na);
        d1 = fmaf(av, bv, d1); n1 = fmaf(bv, bv, n1);
        d2 = fmaf(av, cv, d2); n2 = fmaf(cv, cv, n2);
    }

#pragma unroll
    for (int off = 16; off > 0; off >>= 1) {
        na += __shfl_xor_sync(0xFFFFFFFFu, na, off);
        d1 += __shfl_xor_sync(0xFFFFFFFFu, d1, off);
        n1 += __shfl_xor_sync(0xFFFFFFFFu, n1, off);
        d2 += __shfl_xor_sync(0xFFFFFFFFu, d2, off);
        n2 += __shfl_xor_sync(0xFFFFFFFFu, n2, off);
    }

    if (lane == 0) {
        const float nA = fmaxf(sqrtf(na), EPSN);
        outR[gwarp] = vr ? d1 / (nA * fmaxf(sqrtf(n1), EPSN)) : -1.0f;
        outD[gwarp] = vd ? d2 / (nA * fmaxf(sqrtf(n2), EPSN)) : -1.0f;
    }
}

extern "C" void kernel_launch(void* const* d_in, const int* in_sizes, int n_in,
                              void* d_out, int out_size) {
    const float* x        = (const float*)d_in[0];
    const int* p_frames   = (const int*)d_in[1];
    const int* p_height   = (const int*)d_in[2];
    const int* p_width    = (const int*)d_in[3];
    const int* p_interval = (const int*)d_in[4];
    float* out = (float*)d_out;

    const int total = out_size / 2;            // frames * tpf
    const int D     = in_sizes[0] / total;     // hidden dim

    const int threads = 256;                   // 8 warps/block
    const int blocks  = (total + 7) / 8;

    if (D == 1152) {
        simdiff_pf2_kernel<9><<<blocks, threads>>>(
            x, p_frames, p_height, p_width, p_interval, out, total);
    } else if (D == 1024) {
        simdiff_pf2_kernel<8><<<blocks, threads>>>(
            x, p_frames, p_height, p_width, p_interval, out, total);
    } else if (D == 1280) {
        simdiff_pf2_kernel<10><<<blocks, threads>>>(
            x, p_frames, p_height, p_width, p_interval, out, total);
    } else {
        simdiff_generic_kernel<<<blocks, threads>>>(
            x, p_frames, p_height, p_width, p_interval, out, total, D);
    }
}